// round 1
// baseline (speedup 1.0000x reference)
#include <cuda_runtime.h>

// LRCoulomb: e[b] = FACTOR * sum_{i != j} (1 - fc(d_ij)) * q_i * q_j / d_ij
// fc(d) = exp(1 - 1/(1 - (d/rc)^2)) for d < rc else 0
// B=64, N=512.

#define NATOMS 512
#define RC 4.6f
#define RC2 (RC * RC)
#define INV_RC2 (1.0f / (RC * RC))
#define FACTOR_F 7.199822675975224f

__global__ void lrc_zero_kernel(float* __restrict__ out, int n) {
    int i = blockIdx.x * blockDim.x + threadIdx.x;
    if (i < n) out[i] = 0.0f;
}

__global__ __launch_bounds__(256, 4)
void lrc_coul_kernel(const float* __restrict__ coord,
                     const float* __restrict__ charges,
                     float* __restrict__ out) {
    __shared__ float4 at[NATOMS];       // {x, y, z, q}, 8 KB
    __shared__ float warpsum[8];

    const int mol = blockIdx.y;
    const int tid = threadIdx.x;

    const float* c = coord + (size_t)mol * NATOMS * 3;
    const float* q = charges + (size_t)mol * NATOMS;

    // Cooperative load of all atoms for this molecule into smem.
    for (int a = tid; a < NATOMS; a += 256) {
        at[a] = make_float4(c[a * 3 + 0], c[a * 3 + 1], c[a * 3 + 2], q[a]);
    }
    __syncthreads();

    // Thread t handles row i = blockIdx.x*64 + (t & 63),
    // j segment [(t>>6)*128, +128). All lanes of a warp share (t>>6),
    // so every LDS of at[j] is a full-warp broadcast (conflict-free).
    const int i     = blockIdx.x * 64 + (tid & 63);
    const int jbase = (tid >> 6) * 128;

    const float4 me = at[i];
    float acc = 0.0f;

#pragma unroll 8
    for (int jj = 0; jj < 128; jj++) {
        const int j = jbase + jj;
        const float4 o = at[j];
        const float dx = me.x - o.x;
        const float dy = me.y - o.y;
        const float dz = me.z - o.z;
        const float d2 = fmaf(dx, dx, fmaf(dy, dy, dz * dz));

        const bool valid  = (j != i);
        const float d2s   = valid ? d2 : 1.0f;     // safe value on diagonal
        const float rinv  = rsqrtf(d2s);

        const bool inside = d2s < RC2;
        const float u     = inside ? d2s * INV_RC2 : 0.25f;  // safe value outside
        float fc          = __expf(1.0f - 1.0f / (1.0f - u));
        fc                = inside ? fc : 0.0f;

        const float term = (1.0f - fc) * me.w * o.w * rinv;
        acc += valid ? term : 0.0f;
    }

    // Warp reduction
#pragma unroll
    for (int off = 16; off; off >>= 1)
        acc += __shfl_xor_sync(0xffffffff, acc, off);
    if ((tid & 31) == 0) warpsum[tid >> 5] = acc;
    __syncthreads();

    if (tid < 8) {
        float s = warpsum[tid];
#pragma unroll
        for (int off = 4; off; off >>= 1)
            s += __shfl_xor_sync(0xff, s, off);
        if (tid == 0) atomicAdd(&out[mol], FACTOR_F * s);
    }
}

extern "C" void kernel_launch(void* const* d_in, const int* in_sizes, int n_in,
                              void* d_out, int out_size) {
    const float* coord   = (const float*)d_in[0];   // [64, 512, 3] f32
    const float* charges = (const float*)d_in[1];   // [64, 512]    f32
    // d_in[2] is mask (all true for this problem) — ignored.
    float* out = (float*)d_out;                     // [64] f32

    lrc_zero_kernel<<<1, 64>>>(out, out_size);

    dim3 grid(8, 64);   // 8 row-chunks of 64 rows x 64 molecules
    lrc_coul_kernel<<<grid, 256>>>(coord, charges, out);
}

// round 2
// speedup vs baseline: 1.9229x; 1.9229x over previous
#include <cuda_runtime.h>

// LRCoulomb: e[b] = FACTOR * sum_{i != j} (1 - fc(d_ij)) * q_i * q_j / d_ij
// fc(d) = exp(1 - 1/(1 - (d/rc)^2)) for d < rc else 0.  B=64, N=512.
// Symmetric: compute upper-triangle 128x128 tiles; off-diag tiles counted x2.

#define NATOMS 512
#define TSZ 128
#define RC2 21.159999f            // 4.6^2
#define FACTOR_F 7.199822675975224f

// Tile-pair table: blockIdx.x 0..3 = diagonal tiles, 4..9 = upper off-diag.
__constant__ int c_ti[10] = {0, 1, 2, 3, 0, 0, 0, 1, 1, 2};
__constant__ int c_tj[10] = {0, 1, 2, 3, 1, 2, 3, 2, 3, 3};

__global__ void lrc_zero_kernel(float* __restrict__ out, int n) {
    int i = blockIdx.x * blockDim.x + threadIdx.x;
    if (i < n) out[i] = 0.0f;
}

__global__ __launch_bounds__(256)
void lrc_tile_kernel(const float* __restrict__ coord,
                     const float* __restrict__ charges,
                     float* __restrict__ out) {
    __shared__ float4 sI[TSZ];
    __shared__ float4 sJ[TSZ];
    __shared__ float wsum[8];

    const int mol = blockIdx.y;
    const int tid = threadIdx.x;
    const int tI = c_ti[blockIdx.x];
    const int tJ = c_tj[blockIdx.x];
    const bool diag = blockIdx.x < 4;

    const float* cb = coord + (size_t)mol * NATOMS * 3;
    const float* qb = charges + (size_t)mol * NATOMS;

    if (tid < TSZ) {
        const int a = tI * TSZ + tid;
        sI[tid] = make_float4(cb[a * 3], cb[a * 3 + 1], cb[a * 3 + 2], qb[a]);
    } else {
        const int a = tJ * TSZ + (tid - TSZ);
        sJ[tid - TSZ] = make_float4(cb[a * 3], cb[a * 3 + 1], cb[a * 3 + 2], qb[a]);
    }
    __syncthreads();

    // Thread t: row iLoc = t&127 of tile I, j-segment (t>>7)*64 of tile J.
    // Lanes of a warp share the j index each iteration -> LDS broadcast.
    const int iLoc  = tid & (TSZ - 1);
    const int jbase = (tid >> 7) * 64;
    const float4 me = sI[iLoc];

    float acc = 0.0f;   // sum_j q_j * (1 - fc) / d   (me.w factored out)

    if (diag) {
#pragma unroll 16
        for (int jj = 0; jj < 64; jj++) {
            const int j = jbase + jj;
            const float4 o = sJ[j];
            const float dx = me.x - o.x;
            const float dy = me.y - o.y;
            const float dz = me.z - o.z;
            float d2 = fmaf(dx, dx, fmaf(dy, dy, dz * dz));
            if (j == iLoc) d2 = 1e30f;           // self-pair: ~1e-15 contribution
            const float rinv = rsqrtf(d2);
            acc = fmaf(o.w, rinv, acc);
            const bool inside = d2 < RC2;
            if (__any_sync(0xffffffffu, inside)) {
                if (inside) {
                    const float t = __fdividef(RC2, RC2 - d2);  // 1/(1-(d/rc)^2)
                    const float e = __expf(1.0f - t);
                    acc = fmaf(-e * o.w, rinv, acc);
                }
            }
        }
    } else {
#pragma unroll 16
        for (int jj = 0; jj < 64; jj++) {
            const int j = jbase + jj;
            const float4 o = sJ[j];
            const float dx = me.x - o.x;
            const float dy = me.y - o.y;
            const float dz = me.z - o.z;
            const float d2 = fmaf(dx, dx, fmaf(dy, dy, dz * dz));
            const float rinv = rsqrtf(d2);
            acc = fmaf(o.w, rinv, acc);
            const bool inside = d2 < RC2;
            if (__any_sync(0xffffffffu, inside)) {
                if (inside) {
                    const float t = __fdividef(RC2, RC2 - d2);
                    const float e = __expf(1.0f - t);
                    acc = fmaf(-e * o.w, rinv, acc);
                }
            }
        }
    }

    // Per-thread value: q_i * acc, off-diag tiles count both (i,j) and (j,i).
    float val = me.w * acc;
    if (!diag) val *= 2.0f;

#pragma unroll
    for (int off = 16; off; off >>= 1)
        val += __shfl_xor_sync(0xffffffffu, val, off);
    if ((tid & 31) == 0) wsum[tid >> 5] = val;
    __syncthreads();

    if (tid < 8) {
        float s = wsum[tid];
#pragma unroll
        for (int off = 4; off; off >>= 1)
            s += __shfl_xor_sync(0xffu, s, off);
        if (tid == 0) atomicAdd(&out[mol], FACTOR_F * s);
    }
}

extern "C" void kernel_launch(void* const* d_in, const int* in_sizes, int n_in,
                              void* d_out, int out_size) {
    const float* coord   = (const float*)d_in[0];   // [64, 512, 3] f32
    const float* charges = (const float*)d_in[1];   // [64, 512]    f32
    // d_in[2] is mask (all true) — ignored.
    float* out = (float*)d_out;                     // [64] f32

    lrc_zero_kernel<<<1, 64>>>(out, out_size);

    dim3 grid(10, 64);   // 10 tile-pairs (4 diag + 6 upper) x 64 molecules
    lrc_tile_kernel<<<grid, 256>>>(coord, charges, out);
}

// round 3
// speedup vs baseline: 2.2586x; 1.1746x over previous
#include <cuda_runtime.h>

// LRCoulomb: e[b] = FACTOR * sum_{i != j} (1 - fc(d_ij)) * q_i * q_j / d_ij
// fc(d) = exp(1 - 1/(1 - (d/rc)^2)) for d < rc else 0.  B=64, N=512.
// Symmetric: upper-triangle 128x128 tiles; off-diag tiles counted x2.
// Single kernel: per-molecule scratch + finish-counter (self-resetting for
// graph replay; no zero-kernel needed).

#define NMOL 512
#define TSZ 128
#define NTILES 10
#define RC2 21.159999f            // 4.6^2
#define D2CLAMP 21.0f             // clamp inside arm; err < 1e-57
#define FACTOR_F 7.199822675975224f

__constant__ int c_ti[NTILES] = {0, 1, 2, 3, 0, 0, 0, 1, 1, 2};
__constant__ int c_tj[NTILES] = {0, 1, 2, 3, 1, 2, 3, 2, 3, 3};

__device__ float g_scratch[64];       // zero-init at load; self-resetting
__device__ unsigned int g_count[64];  // zero-init at load; self-resetting

__global__ __launch_bounds__(256)
void lrc_tile_kernel(const float* __restrict__ coord,
                     const float* __restrict__ charges,
                     float* __restrict__ out) {
    __shared__ float4 sI[TSZ];
    __shared__ float4 sJ[TSZ];
    __shared__ float wsum[8];

    const int mol = blockIdx.y;
    const int tid = threadIdx.x;
    const int tI = c_ti[blockIdx.x];
    const int tJ = c_tj[blockIdx.x];
    const bool diag = blockIdx.x < 4;

    const float* cb = coord + (size_t)mol * NMOL * 3;
    const float* qb = charges + (size_t)mol * NMOL;

    if (tid < TSZ) {
        const int a = tI * TSZ + tid;
        sI[tid] = make_float4(cb[a * 3], cb[a * 3 + 1], cb[a * 3 + 2], qb[a]);
    } else {
        const int a = tJ * TSZ + (tid - TSZ);
        sJ[tid - TSZ] = make_float4(cb[a * 3], cb[a * 3 + 1], cb[a * 3 + 2], qb[a]);
    }
    __syncthreads();

    // Thread t: row iLoc = t&127 of tile I, j-segment (t>>7)*64 of tile J.
    // All lanes of a warp share j each iteration -> LDS broadcast.
    const int iLoc  = tid & (TSZ - 1);
    const int jbase = (tid >> 7) * 64;
    const float4 me = sI[iLoc];

    float acc = 0.0f;   // sum_j q_j * (1 - fc) / d   (q_i factored out)

    if (diag) {
#pragma unroll 8
        for (int jj = 0; jj < 64; jj++) {
            const int j = jbase + jj;
            const float4 o = sJ[j];
            const float dx = me.x - o.x;
            const float dy = me.y - o.y;
            const float dz = me.z - o.z;
            float d2 = fmaf(dx, dx, fmaf(dy, dy, dz * dz));
            if (j == iLoc) d2 = 1e30f;           // self-pair -> ~1e-16, negligible
            const float rinv = rsqrtf(d2);
            acc = fmaf(o.w, rinv, acc);
            if (d2 < RC2) {                      // rare (<1% of pairs)
                const float u  = fminf(d2, D2CLAMP);
                const float t  = __fdividef(RC2, RC2 - u);
                const float fc = __expf(1.0f - t);
                acc = fmaf(-fc * o.w, rinv, acc);
            }
        }
    } else {
#pragma unroll 8
        for (int jj = 0; jj < 64; jj++) {
            const int j = jbase + jj;
            const float4 o = sJ[j];
            const float dx = me.x - o.x;
            const float dy = me.y - o.y;
            const float dz = me.z - o.z;
            const float d2 = fmaf(dx, dx, fmaf(dy, dy, dz * dz));
            const float rinv = rsqrtf(d2);
            acc = fmaf(o.w, rinv, acc);
            if (d2 < RC2) {
                const float u  = fminf(d2, D2CLAMP);
                const float t  = __fdividef(RC2, RC2 - u);
                const float fc = __expf(1.0f - t);
                acc = fmaf(-fc * o.w, rinv, acc);
            }
        }
    }

    float val = me.w * acc;
    if (!diag) val *= 2.0f;

#pragma unroll
    for (int off = 16; off; off >>= 1)
        val += __shfl_xor_sync(0xffffffffu, val, off);
    if ((tid & 31) == 0) wsum[tid >> 5] = val;
    __syncthreads();

    if (tid == 0) {
        float s = wsum[0] + wsum[1] + wsum[2] + wsum[3]
                + wsum[4] + wsum[5] + wsum[6] + wsum[7];
        atomicAdd(&g_scratch[mol], s);
        __threadfence();
        const unsigned int old = atomicAdd(&g_count[mol], 1u);
        if (old == NTILES - 1) {
            // Last tile-block for this molecule: publish and reset state
            // so the next graph replay starts clean.
            const float tot = atomicExch(&g_scratch[mol], 0.0f);
            out[mol] = FACTOR_F * tot;
            g_count[mol] = 0;
        }
    }
}

extern "C" void kernel_launch(void* const* d_in, const int* in_sizes, int n_in,
                              void* d_out, int out_size) {
    const float* coord   = (const float*)d_in[0];   // [64, 512, 3] f32
    const float* charges = (const float*)d_in[1];   // [64, 512]    f32
    // d_in[2] is mask (all true) — ignored.
    float* out = (float*)d_out;                     // [64] f32

    dim3 grid(NTILES, 64);   // 10 tile-pairs x 64 molecules
    lrc_tile_kernel<<<grid, 256>>>(coord, charges, out);
}